// round 1
// baseline (speedup 1.0000x reference)
#include <cuda_runtime.h>

#define S_LEN 2048
#define HID   4096
#define NH    32
#define NKV   8
#define HD    128
#define KVD   (NKV*HD)   /* 1024 */
#define QD    (NH*HD)    /* 4096 */
#define ATT_SCALE 0.08838834764831845f

// Scratch (device globals; no runtime allocation allowed)
__device__ float g_Q [S_LEN*QD];   // Q projection, then RoPE'd in place
__device__ float g_K [S_LEN*KVD];  // K projection, then RoPE'd in place
__device__ float g_V [S_LEN*KVD];
__device__ float g_AO[S_LEN*QD];   // attention output [s, h*HD+d]

// ---------------------------------------------------------------------------
// Tiled fp32 GEMM: C[M,N] = A[M,K] @ B[N,K]^T  (both row-major, B = weight)
// 128x128 tile, BK=16, 256 threads, 8x8 per-thread microtile.
// ---------------------------------------------------------------------------
__device__ __forceinline__ void gemm_tile(const float* __restrict__ A,
                                          const float* __restrict__ B,
                                          float* __restrict__ C,
                                          int m0, int n0, int K, int ldc)
{
    __shared__ float As[16][132];
    __shared__ float Bs[16][132];
    const int tid = threadIdx.x;
    const int tx = tid & 15;
    const int ty = tid >> 4;

    float acc[8][8];
#pragma unroll
    for (int i = 0; i < 8; i++)
#pragma unroll
        for (int j = 0; j < 8; j++) acc[i][j] = 0.f;

    for (int kt = 0; kt < K; kt += 16) {
#pragma unroll
        for (int it = 0; it < 2; it++) {
            int fidx = tid + it * 256;      // 0..511
            int row  = fidx >> 2;           // 0..127
            int kk   = (fidx & 3) << 2;     // 0,4,8,12
            float4 va = *(const float4*)(A + (size_t)(m0 + row) * K + kt + kk);
            As[kk+0][row] = va.x; As[kk+1][row] = va.y;
            As[kk+2][row] = va.z; As[kk+3][row] = va.w;
            float4 vb = *(const float4*)(B + (size_t)(n0 + row) * K + kt + kk);
            Bs[kk+0][row] = vb.x; Bs[kk+1][row] = vb.y;
            Bs[kk+2][row] = vb.z; Bs[kk+3][row] = vb.w;
        }
        __syncthreads();
#pragma unroll
        for (int kk = 0; kk < 16; kk++) {
            float4 a0 = *(const float4*)&As[kk][ty*8];
            float4 a1 = *(const float4*)&As[kk][ty*8+4];
            float4 b0 = *(const float4*)&Bs[kk][tx*8];
            float4 b1 = *(const float4*)&Bs[kk][tx*8+4];
            float a[8] = {a0.x,a0.y,a0.z,a0.w,a1.x,a1.y,a1.z,a1.w};
            float b[8] = {b0.x,b0.y,b0.z,b0.w,b1.x,b1.y,b1.z,b1.w};
#pragma unroll
            for (int i = 0; i < 8; i++)
#pragma unroll
                for (int j = 0; j < 8; j++)
                    acc[i][j] = fmaf(a[i], b[j], acc[i][j]);
        }
        __syncthreads();
    }

#pragma unroll
    for (int i = 0; i < 8; i++) {
        float* cp = C + (size_t)(m0 + ty*8 + i) * ldc + n0 + tx*8;
        float4 o0 = {acc[i][0], acc[i][1], acc[i][2], acc[i][3]};
        float4 o1 = {acc[i][4], acc[i][5], acc[i][6], acc[i][7]};
        *(float4*)cp       = o0;
        *(float4*)(cp + 4) = o1;
    }
}

__global__ void __launch_bounds__(256) gemm_qkv_kernel(const float* __restrict__ hs,
                                                       const float* __restrict__ wq,
                                                       const float* __restrict__ wk,
                                                       const float* __restrict__ wv)
{
    int bx = blockIdx.x;
    int m0 = blockIdx.y * 128;
    const float* B; float* C; int n0, ldc;
    if (bx < 32)      { B = wq; C = g_Q; n0 = bx * 128;        ldc = QD;  }
    else if (bx < 40) { B = wk; C = g_K; n0 = (bx - 32) * 128; ldc = KVD; }
    else              { B = wv; C = g_V; n0 = (bx - 40) * 128; ldc = KVD; }
    gemm_tile(hs, B, C, m0, n0, HID, ldc);
}

__global__ void __launch_bounds__(256) gemm_o_kernel(const float* __restrict__ wo,
                                                     float* __restrict__ out)
{
    gemm_tile(g_AO, wo, out, blockIdx.y * 128, blockIdx.x * 128, QD, HID);
}

// ---------------------------------------------------------------------------
// RoPE (rotate-half), in place on g_Q and g_K.
// cos/sin layout: [S, 128], with cos[s, d+64] == cos[s, d] for d < 64.
// ---------------------------------------------------------------------------
__global__ void rope_kernel(const float* __restrict__ cosb,
                            const float* __restrict__ sinb)
{
    int idx = blockIdx.x * blockDim.x + threadIdx.x;
    const int qtot = S_LEN * NH * 64;
    const int ktot = S_LEN * NKV * 64;
    if (idx < qtot) {
        int d = idx & 63;
        int h = (idx >> 6) & 31;
        int s = idx >> 11;               // /(64*32)
        float c  = cosb[s * HD + d];
        float sn = sinb[s * HD + d];
        float* base = g_Q + (size_t)s * QD + h * HD;
        float x1 = base[d], x2 = base[d + 64];
        base[d]      = x1 * c - x2 * sn;
        base[d + 64] = x2 * c + x1 * sn;
    } else if (idx < qtot + ktot) {
        int j = idx - qtot;
        int d = j & 63;
        int h = (j >> 6) & 7;
        int s = j >> 9;                  // /(64*8)
        float c  = cosb[s * HD + d];
        float sn = sinb[s * HD + d];
        float* base = g_K + (size_t)s * KVD + h * HD;
        float x1 = base[d], x2 = base[d + 64];
        base[d]      = x1 * c - x2 * sn;
        base[d + 64] = x2 * c + x1 * sn;
    }
}

// ---------------------------------------------------------------------------
// fp32 causal flash attention, GQA (4 q-heads per kv-head).
// BM = BN = 64, HD = 128, 256 threads. grid = (32 q-tiles, 32 heads).
// ---------------------------------------------------------------------------
#define FLASH_SMEM ((3*64*132 + 64*66 + 3*64) * 4)

__global__ void __launch_bounds__(256) flash_kernel()
{
    extern __shared__ float sm[];
    float* Qs      = sm;                 // [64][132]
    float* Ks      = Qs + 64 * 132;      // [64][132]
    float* Vs      = Ks + 64 * 132;      // [64][132]
    float* Ss      = Vs + 64 * 132;      // [64][66]
    float* m_run   = Ss + 64 * 66;       // [64]
    float* l_run   = m_run + 64;         // [64]
    float* alpha_s = l_run + 64;         // [64]

    const int qt  = 31 - (int)blockIdx.x;   // reversed: heavy tiles first
    const int h   = blockIdx.y;
    const int kvh = h >> 2;
    const int tid = threadIdx.x;
    const int tx  = tid & 15;
    const int ty  = tid >> 4;
    const int r0  = ty * 4;

    // Load Q tile (64 x 128)
#pragma unroll
    for (int it = 0; it < 8; it++) {
        int fidx = tid + it * 256;
        int r  = fidx >> 5;
        int c4 = (fidx & 31) << 2;
        *(float4*)(Qs + r * 132 + c4) =
            *(const float4*)(g_Q + (size_t)(qt * 64 + r) * QD + h * HD + c4);
    }
    if (tid < 64) { m_run[tid] = -3.0e38f; l_run[tid] = 0.f; }

    float o[4][8];
#pragma unroll
    for (int i = 0; i < 4; i++)
#pragma unroll
        for (int j = 0; j < 8; j++) o[i][j] = 0.f;

    __syncthreads();

    for (int jt = 0; jt <= qt; jt++) {
        // Load K and V tiles (each 64 x 128)
#pragma unroll
        for (int it = 0; it < 8; it++) {
            int fidx = tid + it * 256;
            int r  = fidx >> 5;
            int c4 = (fidx & 31) << 2;
            size_t off = (size_t)(jt * 64 + r) * KVD + kvh * HD + c4;
            *(float4*)(Ks + r * 132 + c4) = *(const float4*)(g_K + off);
            *(float4*)(Vs + r * 132 + c4) = *(const float4*)(g_V + off);
        }
        __syncthreads();

        // Scores: S = Q K^T (thread owns rows r0..r0+3, cols tx + 16*j)
        float cc[4][4];
#pragma unroll
        for (int i = 0; i < 4; i++)
#pragma unroll
            for (int j = 0; j < 4; j++) cc[i][j] = 0.f;

#pragma unroll 4
        for (int d = 0; d < 128; d += 4) {
            float4 q[4], k[4];
#pragma unroll
            for (int i = 0; i < 4; i++)
                q[i] = *(const float4*)(Qs + (r0 + i) * 132 + d);
#pragma unroll
            for (int j = 0; j < 4; j++)
                k[j] = *(const float4*)(Ks + (tx + 16 * j) * 132 + d);
#pragma unroll
            for (int i = 0; i < 4; i++)
#pragma unroll
                for (int j = 0; j < 4; j++) {
                    cc[i][j] = fmaf(q[i].x, k[j].x, cc[i][j]);
                    cc[i][j] = fmaf(q[i].y, k[j].y, cc[i][j]);
                    cc[i][j] = fmaf(q[i].z, k[j].z, cc[i][j]);
                    cc[i][j] = fmaf(q[i].w, k[j].w, cc[i][j]);
                }
        }

        const bool diag = (jt == qt);
#pragma unroll
        for (int i = 0; i < 4; i++)
#pragma unroll
            for (int j = 0; j < 4; j++) {
                float v = cc[i][j] * ATT_SCALE;
                int col = tx + 16 * j;
                if (diag && col > r0 + i) v = -1.0e30f;
                Ss[(r0 + i) * 66 + col] = v;
            }
        __syncthreads();

        // Online softmax: 4 lanes per row
        {
            const int row = tid >> 2;
            const int l4  = tid & 3;
            float* srow = Ss + row * 66 + l4 * 16;
            float mloc = -3.0e38f;
#pragma unroll
            for (int t = 0; t < 16; t++) mloc = fmaxf(mloc, srow[t]);
            mloc = fmaxf(mloc, __shfl_xor_sync(0xffffffffu, mloc, 1));
            mloc = fmaxf(mloc, __shfl_xor_sync(0xffffffffu, mloc, 2));
            float mold = m_run[row];
            float mnew = fmaxf(mold, mloc);
            float ssum = 0.f;
#pragma unroll
            for (int t = 0; t < 16; t++) {
                float p = __expf(srow[t] - mnew);
                srow[t] = p;
                ssum += p;
            }
            ssum += __shfl_xor_sync(0xffffffffu, ssum, 1);
            ssum += __shfl_xor_sync(0xffffffffu, ssum, 2);
            if (l4 == 0) {
                float alpha = __expf(mold - mnew);
                l_run[row]   = l_run[row] * alpha + ssum;
                m_run[row]   = mnew;
                alpha_s[row] = alpha;
            }
        }
        __syncthreads();

        // Rescale running O, then O += P @ V
        float al[4];
#pragma unroll
        for (int i = 0; i < 4; i++) al[i] = alpha_s[r0 + i];
#pragma unroll
        for (int i = 0; i < 4; i++)
#pragma unroll
            for (int j = 0; j < 8; j++) o[i][j] *= al[i];

#pragma unroll 4
        for (int kk = 0; kk < 64; kk++) {
            float4 v0 = *(const float4*)(Vs + kk * 132 + tx * 8);
            float4 v1 = *(const float4*)(Vs + kk * 132 + tx * 8 + 4);
#pragma unroll
            for (int i = 0; i < 4; i++) {
                float p = Ss[(r0 + i) * 66 + kk];
                o[i][0] = fmaf(p, v0.x, o[i][0]);
                o[i][1] = fmaf(p, v0.y, o[i][1]);
                o[i][2] = fmaf(p, v0.z, o[i][2]);
                o[i][3] = fmaf(p, v0.w, o[i][3]);
                o[i][4] = fmaf(p, v1.x, o[i][4]);
                o[i][5] = fmaf(p, v1.y, o[i][5]);
                o[i][6] = fmaf(p, v1.z, o[i][6]);
                o[i][7] = fmaf(p, v1.w, o[i][7]);
            }
        }
        __syncthreads();
    }

    // Normalize and write attention output
#pragma unroll
    for (int i = 0; i < 4; i++) {
        float inv = 1.f / l_run[r0 + i];
        float* op = g_AO + (size_t)(qt * 64 + r0 + i) * QD + h * HD + tx * 8;
        float4 o0 = {o[i][0]*inv, o[i][1]*inv, o[i][2]*inv, o[i][3]*inv};
        float4 o1 = {o[i][4]*inv, o[i][5]*inv, o[i][6]*inv, o[i][7]*inv};
        *(float4*)op       = o0;
        *(float4*)(op + 4) = o1;
    }
}

// ---------------------------------------------------------------------------
// Launch
// ---------------------------------------------------------------------------
extern "C" void kernel_launch(void* const* d_in, const int* in_sizes, int n_in,
                              void* d_out, int out_size)
{
    const float* hs   = (const float*)d_in[0];
    const float* cosb = (const float*)d_in[1];
    const float* sinb = (const float*)d_in[2];
    const float* wq   = (const float*)d_in[3];
    const float* wk   = (const float*)d_in[4];
    const float* wv   = (const float*)d_in[5];
    const float* wo   = (const float*)d_in[6];
    // d_in[7..9] = k_cache, v_cache, block_ids: the scatter/gather round-trip
    // is an identity (block_ids are distinct), so they are unused.
    float* out = (float*)d_out;

    cudaFuncSetAttribute(flash_kernel,
                         cudaFuncAttributeMaxDynamicSharedMemorySize, FLASH_SMEM);

    // 1) QKV projections (fused launch: bx 0..31 -> Q, 32..39 -> K, 40..47 -> V)
    gemm_qkv_kernel<<<dim3(48, 16), 256>>>(hs, wq, wk, wv);

    // 2) RoPE on Q and K
    int total = S_LEN * NH * 64 + S_LEN * NKV * 64;
    rope_kernel<<<(total + 255) / 256, 256>>>(cosb, sinb);

    // 3) Causal GQA flash attention
    flash_kernel<<<dim3(32, 32), 256, FLASH_SMEM>>>();

    // 4) Output projection into d_out
    gemm_o_kernel<<<dim3(32, 16), 256>>>(wo, out);
}

// round 4
// speedup vs baseline: 1.8329x; 1.8329x over previous
#include <cuda_runtime.h>
#include <cuda_bf16.h>
#include <cstdint>

#define S_LEN 2048
#define HID   4096
#define NH    32
#define NKV   8
#define HD    128
#define KVD   (NKV*HD)   /* 1024 */
#define QD    (NH*HD)    /* 4096 */
#define WROWS (QD+2*KVD) /* 6144 */
#define ATT_SCALE 0.08838834764831845f

// ---------------------------------------------------------------------------
// Scratch (device globals; no runtime allocation allowed)
// ---------------------------------------------------------------------------
__device__ float g_Q [S_LEN*QD];   // Q projection, RoPE'd in place (fp32)
__device__ float g_K [S_LEN*KVD];  // K projection, RoPE'd in place (fp32)
__device__ float g_V [S_LEN*KVD];
__device__ float g_AO[S_LEN*QD];   // attention output (fp32)

// bf16 split operands (x = hi + lo)
__device__ __nv_bfloat16 g_hsH[S_LEN*HID], g_hsL[S_LEN*HID];
__device__ __nv_bfloat16 g_WH [WROWS*HID], g_WL [WROWS*HID];   // wq|wk|wv stacked
__device__ __nv_bfloat16 g_WOH[HID*QD],    g_WOL[HID*QD];
__device__ __nv_bfloat16 g_AOH[S_LEN*QD],  g_AOL[S_LEN*QD];

// ---------------------------------------------------------------------------
// mma.sync helpers (sm_80-level, compiles for compute_103)
// ---------------------------------------------------------------------------
__device__ __forceinline__ uint32_t smem_u32(const void* p) {
    uint32_t a;
    asm("{ .reg .u64 t; cvta.to.shared.u64 t, %1; cvt.u32.u64 %0, t; }"
        : "=r"(a) : "l"(p));
    return a;
}

__device__ __forceinline__ void ldsm_x4(uint32_t* r, uint32_t addr) {
    asm volatile("ldmatrix.sync.aligned.m8n8.x4.shared.b16 {%0,%1,%2,%3}, [%4];"
        : "=r"(r[0]), "=r"(r[1]), "=r"(r[2]), "=r"(r[3]) : "r"(addr));
}

__device__ __forceinline__ void mma16816(float* d, const uint32_t* a,
                                         const uint32_t* b) {
    asm volatile(
        "mma.sync.aligned.m16n8k16.row.col.f32.bf16.bf16.f32 "
        "{%0,%1,%2,%3},{%4,%5,%6,%7},{%8,%9},{%0,%1,%2,%3};"
        : "+f"(d[0]), "+f"(d[1]), "+f"(d[2]), "+f"(d[3])
        : "r"(a[0]), "r"(a[1]), "r"(a[2]), "r"(a[3]), "r"(b[0]), "r"(b[1]));
}

__device__ __forceinline__ void cp16(uint32_t saddr, const void* g) {
    asm volatile("cp.async.cg.shared.global [%0], [%1], 16;"
        :: "r"(saddr), "l"(g) : "memory");
}

// ---------------------------------------------------------------------------
// Split-bf16 HMMA GEMM: C[128,128] = (Ah+Al)[128,K] @ (Bh+Bl)[128,K]^T
// 256 threads, warp grid 2(m) x 4(n), warp tile 64x32. BK=32, double buffered.
// ---------------------------------------------------------------------------
#define LDT      40                  /* padded row length (bf16 elems) */
#define TILE_B   (128*LDT*2)         /* 10240 B per tile */
#define STAGE_B  (4*TILE_B)          /* Ah, Al, Bh, Bl */
#define GEMM_SMEM (2*STAGE_B)        /* 81920 B */

__device__ __forceinline__ void mma_gemm(
    const __nv_bfloat16* __restrict__ pAh, const __nv_bfloat16* __restrict__ pAl,
    const __nv_bfloat16* __restrict__ pBh, const __nv_bfloat16* __restrict__ pBl,
    int K, float* __restrict__ Cp, int ldc)
{
    extern __shared__ char smc[];
    const uint32_t smb = smem_u32(smc);
    const int tid = threadIdx.x;
    const int wid = tid >> 5;
    const int l   = tid & 31;
    const int wm  = wid & 1;     // 0..1  (64 rows each)
    const int wn  = wid >> 1;    // 0..3  (32 cols each)

    float acc[4][4][4] = {};

    const int nk = K >> 5;       // number of BK=32 stages

    // stage issuer: 2048 16B-chunks per stage, 8 per thread, tile idx static
#define ISSUE_STAGE(s, kb) do {                                              \
        uint32_t sb_ = smb + (s) * STAGE_B;                                  \
        _Pragma("unroll")                                                    \
        for (int t = 0; t < 8; t++) {                                        \
            const int tile = t >> 1;                                         \
            int idx2 = tid + (t & 1) * 256;   /* 0..511 */                   \
            int row  = idx2 >> 2;                                            \
            int ch   = idx2 & 3;                                             \
            const __nv_bfloat16* src =                                       \
                (tile == 0) ? pAh : (tile == 1) ? pAl :                      \
                (tile == 2) ? pBh : pBl;                                     \
            cp16(sb_ + tile * TILE_B + (row * LDT + ch * 8) * 2,             \
                 src + (size_t)row * K + (kb) + ch * 8);                     \
        }                                                                    \
        asm volatile("cp.async.commit_group;" ::: "memory");                 \
    } while (0)

    ISSUE_STAGE(0, 0);

    for (int kt = 0; kt < nk; kt++) {
        const int s = kt & 1;
        if (kt + 1 < nk) {
            ISSUE_STAGE(s ^ 1, (kt + 1) << 5);
            asm volatile("cp.async.wait_group 1;" ::: "memory");
        } else {
            asm volatile("cp.async.wait_group 0;" ::: "memory");
        }
        __syncthreads();

        const uint32_t sb  = smb + s * STAGE_B;
        const uint32_t aAh = sb;
        const uint32_t aAl = sb + TILE_B;
        const uint32_t aBh = sb + 2 * TILE_B;
        const uint32_t aBl = sb + 3 * TILE_B;

#pragma unroll
        for (int ks = 0; ks < 2; ks++) {
            const int k0 = ks * 16;
            uint32_t ah[4][4], al[4][4], bh[2][4], bl[2][4];
#pragma unroll
            for (int mt = 0; mt < 4; mt++) {
                uint32_t off = (uint32_t)((wm * 64 + mt * 16 + (l & 15)) * LDT
                                          + k0 + 8 * (l >> 4)) * 2;
                ldsm_x4(ah[mt], aAh + off);
                ldsm_x4(al[mt], aAl + off);
            }
#pragma unroll
            for (int p = 0; p < 2; p++) {
                uint32_t off = (uint32_t)((wn * 32 + p * 16 + 8 * (l >> 4) + (l & 7)) * LDT
                                          + k0 + 8 * ((l >> 3) & 1)) * 2;
                ldsm_x4(bh[p], aBh + off);
                ldsm_x4(bl[p], aBl + off);
            }
#pragma unroll
            for (int mt = 0; mt < 4; mt++)
#pragma unroll
                for (int nt = 0; nt < 4; nt++) {
                    const uint32_t* Bh_ = &bh[nt >> 1][(nt & 1) * 2];
                    const uint32_t* Bl_ = &bl[nt >> 1][(nt & 1) * 2];
                    mma16816(acc[mt][nt], ah[mt], Bh_);
                    mma16816(acc[mt][nt], ah[mt], Bl_);
                    mma16816(acc[mt][nt], al[mt], Bh_);
                }
        }
        __syncthreads();
    }

    // Epilogue: fp32 accum -> C
    const int m_base = wm * 64;
    const int n_base = wn * 32;
#pragma unroll
    for (int mt = 0; mt < 4; mt++)
#pragma unroll
        for (int nt = 0; nt < 4; nt++) {
            int row = m_base + mt * 16 + (l >> 2);
            int col = n_base + nt * 8 + 2 * (l & 3);
            float2 v0 = {acc[mt][nt][0], acc[mt][nt][1]};
            float2 v1 = {acc[mt][nt][2], acc[mt][nt][3]};
            *(float2*)(Cp + (size_t)row * ldc + col)       = v0;
            *(float2*)(Cp + (size_t)(row + 8) * ldc + col) = v1;
        }
#undef ISSUE_STAGE
}

__global__ void __launch_bounds__(256) qkv_mma_kernel()
{
    const int bx = blockIdx.x;
    const int m0 = blockIdx.y * 128;
    float* C; int ldc, n0;
    if (bx < 32)      { C = g_Q; ldc = QD;  n0 = bx << 7; }
    else if (bx < 40) { C = g_K; ldc = KVD; n0 = (bx - 32) << 7; }
    else              { C = g_V; ldc = KVD; n0 = (bx - 40) << 7; }
    mma_gemm(g_hsH + (size_t)m0 * HID, g_hsL + (size_t)m0 * HID,
             g_WH  + (size_t)(bx << 7) * HID, g_WL + (size_t)(bx << 7) * HID,
             HID, C + (size_t)m0 * ldc + n0, ldc);
}

__global__ void __launch_bounds__(256) o_mma_kernel(float* __restrict__ out)
{
    const int m0 = blockIdx.y * 128;
    const int n0 = blockIdx.x * 128;
    mma_gemm(g_AOH + (size_t)m0 * QD, g_AOL + (size_t)m0 * QD,
             g_WOH + (size_t)n0 * QD, g_WOL + (size_t)n0 * QD,
             QD, out + (size_t)m0 * HID + n0, HID);
}

// ---------------------------------------------------------------------------
// fp32 -> bf16 hi/lo split. Destination is selected INSIDE device code —
// __device__ symbols must never be passed as kernel args from host (the host
// shadow symbol is a host address; GB300's ATS dereferences it silently).
// ---------------------------------------------------------------------------
__device__ __forceinline__ void cvt4(const float* __restrict__ src,
                                     __nv_bfloat16* __restrict__ hi,
                                     __nv_bfloat16* __restrict__ lo, int i)
{
    float4 x = *(const float4*)(src + i);
    __nv_bfloat16 h0 = __float2bfloat16(x.x);
    __nv_bfloat16 h1 = __float2bfloat16(x.y);
    __nv_bfloat16 h2 = __float2bfloat16(x.z);
    __nv_bfloat16 h3 = __float2bfloat16(x.w);
    __nv_bfloat16 l0 = __float2bfloat16(x.x - __bfloat162float(h0));
    __nv_bfloat16 l1 = __float2bfloat16(x.y - __bfloat162float(h1));
    __nv_bfloat16 l2 = __float2bfloat16(x.z - __bfloat162float(h2));
    __nv_bfloat16 l3 = __float2bfloat16(x.w - __bfloat162float(h3));
    __nv_bfloat162 hv0{h0, h1}, hv1{h2, h3}, lv0{l0, l1}, lv1{l2, l3};
    *(__nv_bfloat162*)(hi + i)     = hv0;
    *(__nv_bfloat162*)(hi + i + 2) = hv1;
    *(__nv_bfloat162*)(lo + i)     = lv0;
    *(__nv_bfloat162*)(lo + i + 2) = lv1;
}

__global__ void cvt_sel_kernel(const float* __restrict__ src, int which,
                               size_t off, int n)
{
    int i = (blockIdx.x * blockDim.x + threadIdx.x) << 2;
    if (i >= n) return;
    __nv_bfloat16 *hi, *lo;
    if (which == 0)      { hi = g_hsH;      lo = g_hsL;      }
    else if (which == 1) { hi = g_WH + off; lo = g_WL + off; }
    else                 { hi = g_WOH;      lo = g_WOL;      }
    cvt4(src, hi, lo, i);
}

__global__ void cvt_ao_kernel()
{
    int i = (blockIdx.x * blockDim.x + threadIdx.x) << 2;
    if (i < S_LEN * QD) cvt4(g_AO, g_AOH, g_AOL, i);
}

// ---------------------------------------------------------------------------
// RoPE (rotate-half), in place on g_Q and g_K (fp32).
// ---------------------------------------------------------------------------
__global__ void rope_kernel(const float* __restrict__ cosb,
                            const float* __restrict__ sinb)
{
    int idx = blockIdx.x * blockDim.x + threadIdx.x;
    const int qtot = S_LEN * NH * 64;
    const int ktot = S_LEN * NKV * 64;
    if (idx < qtot) {
        int d = idx & 63;
        int h = (idx >> 6) & 31;
        int s = idx >> 11;
        float c  = cosb[s * HD + d];
        float sn = sinb[s * HD + d];
        float* base = g_Q + (size_t)s * QD + h * HD;
        float x1 = base[d], x2 = base[d + 64];
        base[d]      = x1 * c - x2 * sn;
        base[d + 64] = x2 * c + x1 * sn;
    } else if (idx < qtot + ktot) {
        int j = idx - qtot;
        int d = j & 63;
        int h = (j >> 6) & 7;
        int s = j >> 9;
        float c  = cosb[s * HD + d];
        float sn = sinb[s * HD + d];
        float* base = g_K + (size_t)s * KVD + h * HD;
        float x1 = base[d], x2 = base[d + 64];
        base[d]      = x1 * c - x2 * sn;
        base[d + 64] = x2 * c + x1 * sn;
    }
}

// ---------------------------------------------------------------------------
// fp32 causal flash attention, GQA (unchanged — passed round 1).
// ---------------------------------------------------------------------------
#define FLASH_SMEM ((3*64*132 + 64*66 + 3*64) * 4)

__global__ void __launch_bounds__(256) flash_kernel()
{
    extern __shared__ float smf[];
    float* Qs      = smf;
    float* Ks      = Qs + 64 * 132;
    float* Vs      = Ks + 64 * 132;
    float* Ss      = Vs + 64 * 132;
    float* m_run   = Ss + 64 * 66;
    float* l_run   = m_run + 64;
    float* alpha_s = l_run + 64;

    const int qt  = 31 - (int)blockIdx.x;
    const int h   = blockIdx.y;
    const int kvh = h >> 2;
    const int tid = threadIdx.x;
    const int tx  = tid & 15;
    const int ty  = tid >> 4;
    const int r0  = ty * 4;

#pragma unroll
    for (int it = 0; it < 8; it++) {
        int fidx = tid + it * 256;
        int r  = fidx >> 5;
        int c4 = (fidx & 31) << 2;
        *(float4*)(Qs + r * 132 + c4) =
            *(const float4*)(g_Q + (size_t)(qt * 64 + r) * QD + h * HD + c4);
    }
    if (tid < 64) { m_run[tid] = -3.0e38f; l_run[tid] = 0.f; }

    float o[4][8];
#pragma unroll
    for (int i = 0; i < 4; i++)
#pragma unroll
        for (int j = 0; j < 8; j++) o[i][j] = 0.f;

    __syncthreads();

    for (int jt = 0; jt <= qt; jt++) {
#pragma unroll
        for (int it = 0; it < 8; it++) {
            int fidx = tid + it * 256;
            int r  = fidx >> 5;
            int c4 = (fidx & 31) << 2;
            size_t off = (size_t)(jt * 64 + r) * KVD + kvh * HD + c4;
            *(float4*)(Ks + r * 132 + c4) = *(const float4*)(g_K + off);
            *(float4*)(Vs + r * 132 + c4) = *(const float4*)(g_V + off);
        }
        __syncthreads();

        float cc[4][4];
#pragma unroll
        for (int i = 0; i < 4; i++)
#pragma unroll
            for (int j = 0; j < 4; j++) cc[i][j] = 0.f;

#pragma unroll 4
        for (int d = 0; d < 128; d += 4) {
            float4 q[4], kk4[4];
#pragma unroll
            for (int i = 0; i < 4; i++)
                q[i] = *(const float4*)(Qs + (r0 + i) * 132 + d);
#pragma unroll
            for (int j = 0; j < 4; j++)
                kk4[j] = *(const float4*)(Ks + (tx + 16 * j) * 132 + d);
#pragma unroll
            for (int i = 0; i < 4; i++)
#pragma unroll
                for (int j = 0; j < 4; j++) {
                    cc[i][j] = fmaf(q[i].x, kk4[j].x, cc[i][j]);
                    cc[i][j] = fmaf(q[i].y, kk4[j].y, cc[i][j]);
                    cc[i][j] = fmaf(q[i].z, kk4[j].z, cc[i][j]);
                    cc[i][j] = fmaf(q[i].w, kk4[j].w, cc[i][j]);
                }
        }

        const bool diag = (jt == qt);
#pragma unroll
        for (int i = 0; i < 4; i++)
#pragma unroll
            for (int j = 0; j < 4; j++) {
                float v = cc[i][j] * ATT_SCALE;
                int col = tx + 16 * j;
                if (diag && col > r0 + i) v = -1.0e30f;
                Ss[(r0 + i) * 66 + col] = v;
            }
        __syncthreads();

        {
            const int row = tid >> 2;
            const int l4  = tid & 3;
            float* srow = Ss + row * 66 + l4 * 16;
            float mloc = -3.0e38f;
#pragma unroll
            for (int t = 0; t < 16; t++) mloc = fmaxf(mloc, srow[t]);
            mloc = fmaxf(mloc, __shfl_xor_sync(0xffffffffu, mloc, 1));
            mloc = fmaxf(mloc, __shfl_xor_sync(0xffffffffu, mloc, 2));
            float mold = m_run[row];
            float mnew = fmaxf(mold, mloc);
            float ssum = 0.f;
#pragma unroll
            for (int t = 0; t < 16; t++) {
                float p = __expf(srow[t] - mnew);
                srow[t] = p;
                ssum += p;
            }
            ssum += __shfl_xor_sync(0xffffffffu, ssum, 1);
            ssum += __shfl_xor_sync(0xffffffffu, ssum, 2);
            if (l4 == 0) {
                float alpha = __expf(mold - mnew);
                l_run[row]   = l_run[row] * alpha + ssum;
                m_run[row]   = mnew;
                alpha_s[row] = alpha;
            }
        }
        __syncthreads();

        float al4[4];
#pragma unroll
        for (int i = 0; i < 4; i++) al4[i] = alpha_s[r0 + i];
#pragma unroll
        for (int i = 0; i < 4; i++)
#pragma unroll
            for (int j = 0; j < 8; j++) o[i][j] *= al4[i];

#pragma unroll 4
        for (int kk = 0; kk < 64; kk++) {
            float4 v0 = *(const float4*)(Vs + kk * 132 + tx * 8);
            float4 v1 = *(const float4*)(Vs + kk * 132 + tx * 8 + 4);
#pragma unroll
            for (int i = 0; i < 4; i++) {
                float p = Ss[(r0 + i) * 66 + kk];
                o[i][0] = fmaf(p, v0.x, o[i][0]);
                o[i][1] = fmaf(p, v0.y, o[i][1]);
                o[i][2] = fmaf(p, v0.z, o[i][2]);
                o[i][3] = fmaf(p, v0.w, o[i][3]);
                o[i][4] = fmaf(p, v1.x, o[i][4]);
                o[i][5] = fmaf(p, v1.y, o[i][5]);
                o[i][6] = fmaf(p, v1.z, o[i][6]);
                o[i][7] = fmaf(p, v1.w, o[i][7]);
            }
        }
        __syncthreads();
    }

#pragma unroll
    for (int i = 0; i < 4; i++) {
        float inv = 1.f / l_run[r0 + i];
        float* op = g_AO + (size_t)(qt * 64 + r0 + i) * QD + h * HD + tx * 8;
        float4 o0 = {o[i][0]*inv, o[i][1]*inv, o[i][2]*inv, o[i][3]*inv};
        float4 o1 = {o[i][4]*inv, o[i][5]*inv, o[i][6]*inv, o[i][7]*inv};
        *(float4*)op       = o0;
        *(float4*)(op + 4) = o1;
    }
}

// ---------------------------------------------------------------------------
// Launch
// ---------------------------------------------------------------------------
extern "C" void kernel_launch(void* const* d_in, const int* in_sizes, int n_in,
                              void* d_out, int out_size)
{
    const float* hs   = (const float*)d_in[0];
    const float* cosb = (const float*)d_in[1];
    const float* sinb = (const float*)d_in[2];
    const float* wq   = (const float*)d_in[3];
    const float* wk   = (const float*)d_in[4];
    const float* wv   = (const float*)d_in[5];
    const float* wo   = (const float*)d_in[6];
    // d_in[7..9] (k_cache, v_cache, block_ids): scatter/gather is an identity.
    float* out = (float*)d_out;

    cudaFuncSetAttribute(qkv_mma_kernel,
                         cudaFuncAttributeMaxDynamicSharedMemorySize, GEMM_SMEM);
    cudaFuncSetAttribute(o_mma_kernel,
                         cudaFuncAttributeMaxDynamicSharedMemorySize, GEMM_SMEM);
    cudaFuncSetAttribute(flash_kernel,
                         cudaFuncAttributeMaxDynamicSharedMemorySize, FLASH_SMEM);

    // 1) fp32 -> split-bf16 conversions (dst chosen device-side via tag)
    {
        const int nh = S_LEN * HID;
        cvt_sel_kernel<<<nh / 1024, 256>>>(hs, 0, 0, nh);
        const int nq = QD * HID;
        cvt_sel_kernel<<<nq / 1024, 256>>>(wq, 1, 0, nq);
        const int nk = KVD * HID;
        cvt_sel_kernel<<<nk / 1024, 256>>>(wk, 1, (size_t)QD * HID, nk);
        cvt_sel_kernel<<<nk / 1024, 256>>>(wv, 1, (size_t)(QD + KVD) * HID, nk);
        const int no = HID * QD;
        cvt_sel_kernel<<<no / 1024, 256>>>(wo, 2, 0, no);
    }

    // 2) QKV projections on HMMA (bx 0..31 -> Q, 32..39 -> K, 40..47 -> V)
    qkv_mma_kernel<<<dim3(48, 16), 256, GEMM_SMEM>>>();

    // 3) RoPE on Q and K (fp32)
    {
        int total = S_LEN * NH * 64 + S_LEN * NKV * 64;
        rope_kernel<<<(total + 255) / 256, 256>>>(cosb, sinb);
    }

    // 4) Causal GQA flash attention (fp32)
    flash_kernel<<<dim3(32, 32), 256, FLASH_SMEM>>>();

    // 5) AO -> split-bf16, then O projection on HMMA
    cvt_ao_kernel<<<(S_LEN * QD) / 1024, 256>>>();
    o_mma_kernel<<<dim3(32, 16), 256, GEMM_SMEM>>>(out);
}

// round 6
// speedup vs baseline: 2.9060x; 1.5855x over previous
#include <cuda_runtime.h>
#include <cuda_bf16.h>
#include <cstdint>

#define S_LEN 2048
#define HID   4096
#define NH    32
#define NKV   8
#define HD    128
#define KVD   (NKV*HD)   /* 1024 */
#define QD    (NH*HD)    /* 4096 */
#define WROWS (QD+2*KVD) /* 6144 */
#define ATT_SCALE 0.08838834764831845f

// ---------------------------------------------------------------------------
// Scratch (device globals; no runtime allocation allowed)
// ---------------------------------------------------------------------------
__device__ float g_Q [S_LEN*QD];   // Q projection, RoPE'd in place (fp32)
__device__ float g_K [S_LEN*KVD];  // K projection, RoPE'd in place (fp32)
__device__ float g_V [S_LEN*KVD];
__device__ float g_AO[S_LEN*QD];   // attention output (fp32)

// bf16 split operands (x = hi + lo)
__device__ __nv_bfloat16 g_hsH[S_LEN*HID], g_hsL[S_LEN*HID];
__device__ __nv_bfloat16 g_WH [WROWS*HID], g_WL [WROWS*HID];   // wq|wk|wv stacked
__device__ __nv_bfloat16 g_WOH[HID*QD],    g_WOL[HID*QD];
__device__ __nv_bfloat16 g_AOH[S_LEN*QD],  g_AOL[S_LEN*QD];
// split Q/K/V for HMMA flash (post-RoPE)
__device__ __nv_bfloat16 g_QH[S_LEN*QD],  g_QL[S_LEN*QD];
__device__ __nv_bfloat16 g_KH[S_LEN*KVD], g_KL[S_LEN*KVD];
__device__ __nv_bfloat16 g_VH[S_LEN*KVD], g_VL[S_LEN*KVD];

// ---------------------------------------------------------------------------
// mma.sync helpers (sm_80-level, compiles for compute_103)
// ---------------------------------------------------------------------------
__device__ __forceinline__ uint32_t smem_u32(const void* p) {
    uint32_t a;
    asm("{ .reg .u64 t; cvta.to.shared.u64 t, %1; cvt.u32.u64 %0, t; }"
        : "=r"(a) : "l"(p));
    return a;
}

__device__ __forceinline__ void ldsm_x4(uint32_t* r, uint32_t addr) {
    asm volatile("ldmatrix.sync.aligned.m8n8.x4.shared.b16 {%0,%1,%2,%3}, [%4];"
        : "=r"(r[0]), "=r"(r[1]), "=r"(r[2]), "=r"(r[3]) : "r"(addr));
}

__device__ __forceinline__ void ldsm_x4_t(uint32_t* r, uint32_t addr) {
    asm volatile("ldmatrix.sync.aligned.m8n8.x4.trans.shared.b16 {%0,%1,%2,%3}, [%4];"
        : "=r"(r[0]), "=r"(r[1]), "=r"(r[2]), "=r"(r[3]) : "r"(addr));
}

__device__ __forceinline__ void mma16816(float* d, const uint32_t* a,
                                         const uint32_t* b) {
    asm volatile(
        "mma.sync.aligned.m16n8k16.row.col.f32.bf16.bf16.f32 "
        "{%0,%1,%2,%3},{%4,%5,%6,%7},{%8,%9},{%0,%1,%2,%3};"
        : "+f"(d[0]), "+f"(d[1]), "+f"(d[2]), "+f"(d[3])
        : "r"(a[0]), "r"(a[1]), "r"(a[2]), "r"(a[3]), "r"(b[0]), "r"(b[1]));
}

__device__ __forceinline__ void cp16(uint32_t saddr, const void* g) {
    asm volatile("cp.async.cg.shared.global [%0], [%1], 16;"
        :: "r"(saddr), "l"(g) : "memory");
}

// pack two f32 -> bf16x2 (lo first)
__device__ __forceinline__ uint32_t pack_bf(float lo, float hi) {
    uint32_t r;
    asm("cvt.rn.bf16x2.f32 %0, %1, %2;" : "=r"(r) : "f"(hi), "f"(lo));
    return r;
}

// ---------------------------------------------------------------------------
// Split-bf16 HMMA GEMM: C[128,128] = (Ah+Al)[128,K] @ (Bh+Bl)[128,K]^T
// 256 threads, warp grid 2(m) x 4(n), warp tile 64x32. BK=32, double buffered.
// ---------------------------------------------------------------------------
#define LDT      40
#define TILE_B   (128*LDT*2)
#define STAGE_B  (4*TILE_B)
#define GEMM_SMEM (2*STAGE_B)

__device__ __forceinline__ void mma_gemm(
    const __nv_bfloat16* __restrict__ pAh, const __nv_bfloat16* __restrict__ pAl,
    const __nv_bfloat16* __restrict__ pBh, const __nv_bfloat16* __restrict__ pBl,
    int K, float* __restrict__ Cp, int ldc)
{
    extern __shared__ char smc[];
    const uint32_t smb = smem_u32(smc);
    const int tid = threadIdx.x;
    const int wid = tid >> 5;
    const int l   = tid & 31;
    const int wm  = wid & 1;
    const int wn  = wid >> 1;

    float acc[4][4][4] = {};
    const int nk = K >> 5;

#define ISSUE_STAGE(s, kb) do {                                              \
        uint32_t sb_ = smb + (s) * STAGE_B;                                  \
        _Pragma("unroll")                                                    \
        for (int t = 0; t < 8; t++) {                                        \
            const int tile = t >> 1;                                         \
            int idx2 = tid + (t & 1) * 256;                                  \
            int row  = idx2 >> 2;                                            \
            int ch   = idx2 & 3;                                             \
            const __nv_bfloat16* src =                                       \
                (tile == 0) ? pAh : (tile == 1) ? pAl :                      \
                (tile == 2) ? pBh : pBl;                                     \
            cp16(sb_ + tile * TILE_B + (row * LDT + ch * 8) * 2,             \
                 src + (size_t)row * K + (kb) + ch * 8);                     \
        }                                                                    \
        asm volatile("cp.async.commit_group;" ::: "memory");                 \
    } while (0)

    ISSUE_STAGE(0, 0);

    for (int kt = 0; kt < nk; kt++) {
        const int s = kt & 1;
        if (kt + 1 < nk) {
            ISSUE_STAGE(s ^ 1, (kt + 1) << 5);
            asm volatile("cp.async.wait_group 1;" ::: "memory");
        } else {
            asm volatile("cp.async.wait_group 0;" ::: "memory");
        }
        __syncthreads();

        const uint32_t sb  = smb + s * STAGE_B;
        const uint32_t aAh = sb;
        const uint32_t aAl = sb + TILE_B;
        const uint32_t aBh = sb + 2 * TILE_B;
        const uint32_t aBl = sb + 3 * TILE_B;

#pragma unroll
        for (int ks = 0; ks < 2; ks++) {
            const int k0 = ks * 16;
            uint32_t ah[4][4], al[4][4], bh[2][4], bl[2][4];
#pragma unroll
            for (int mt = 0; mt < 4; mt++) {
                uint32_t off = (uint32_t)((wm * 64 + mt * 16 + (l & 15)) * LDT
                                          + k0 + 8 * (l >> 4)) * 2;
                ldsm_x4(ah[mt], aAh + off);
                ldsm_x4(al[mt], aAl + off);
            }
#pragma unroll
            for (int p = 0; p < 2; p++) {
                uint32_t off = (uint32_t)((wn * 32 + p * 16 + 8 * (l >> 4) + (l & 7)) * LDT
                                          + k0 + 8 * ((l >> 3) & 1)) * 2;
                ldsm_x4(bh[p], aBh + off);
                ldsm_x4(bl[p], aBl + off);
            }
#pragma unroll
            for (int mt = 0; mt < 4; mt++)
#pragma unroll
                for (int nt = 0; nt < 4; nt++) {
                    const uint32_t* Bh_ = &bh[nt >> 1][(nt & 1) * 2];
                    const uint32_t* Bl_ = &bl[nt >> 1][(nt & 1) * 2];
                    mma16816(acc[mt][nt], ah[mt], Bh_);
                    mma16816(acc[mt][nt], ah[mt], Bl_);
                    mma16816(acc[mt][nt], al[mt], Bh_);
                }
        }
        __syncthreads();
    }

    const int m_base = wm * 64;
    const int n_base = wn * 32;
#pragma unroll
    for (int mt = 0; mt < 4; mt++)
#pragma unroll
        for (int nt = 0; nt < 4; nt++) {
            int row = m_base + mt * 16 + (l >> 2);
            int col = n_base + nt * 8 + 2 * (l & 3);
            float2 v0 = {acc[mt][nt][0], acc[mt][nt][1]};
            float2 v1 = {acc[mt][nt][2], acc[mt][nt][3]};
            *(float2*)(Cp + (size_t)row * ldc + col)       = v0;
            *(float2*)(Cp + (size_t)(row + 8) * ldc + col) = v1;
        }
#undef ISSUE_STAGE
}

__global__ void __launch_bounds__(256) qkv_mma_kernel()
{
    const int bx = blockIdx.x;
    const int m0 = blockIdx.y * 128;
    float* C; int ldc, n0;
    if (bx < 32)      { C = g_Q; ldc = QD;  n0 = bx << 7; }
    else if (bx < 40) { C = g_K; ldc = KVD; n0 = (bx - 32) << 7; }
    else              { C = g_V; ldc = KVD; n0 = (bx - 40) << 7; }
    mma_gemm(g_hsH + (size_t)m0 * HID, g_hsL + (size_t)m0 * HID,
             g_WH  + (size_t)(bx << 7) * HID, g_WL + (size_t)(bx << 7) * HID,
             HID, C + (size_t)m0 * ldc + n0, ldc);
}

__global__ void __launch_bounds__(256) o_mma_kernel(float* __restrict__ out)
{
    const int m0 = blockIdx.y * 128;
    const int n0 = blockIdx.x * 128;
    mma_gemm(g_AOH + (size_t)m0 * QD, g_AOL + (size_t)m0 * QD,
             g_WOH + (size_t)n0 * QD, g_WOL + (size_t)n0 * QD,
             QD, out + (size_t)m0 * HID + n0, HID);
}

// ---------------------------------------------------------------------------
// fp32 -> bf16 hi/lo split (dst selected device-side; never pass __device__
// symbols from host — ATS makes the GPU silently write host RAM).
// ---------------------------------------------------------------------------
__device__ __forceinline__ void cvt4(const float* __restrict__ src,
                                     __nv_bfloat16* __restrict__ hi,
                                     __nv_bfloat16* __restrict__ lo, int i)
{
    float4 x = *(const float4*)(src + i);
    __nv_bfloat16 h0 = __float2bfloat16(x.x);
    __nv_bfloat16 h1 = __float2bfloat16(x.y);
    __nv_bfloat16 h2 = __float2bfloat16(x.z);
    __nv_bfloat16 h3 = __float2bfloat16(x.w);
    __nv_bfloat16 l0 = __float2bfloat16(x.x - __bfloat162float(h0));
    __nv_bfloat16 l1 = __float2bfloat16(x.y - __bfloat162float(h1));
    __nv_bfloat16 l2 = __float2bfloat16(x.z - __bfloat162float(h2));
    __nv_bfloat16 l3 = __float2bfloat16(x.w - __bfloat162float(h3));
    __nv_bfloat162 hv0{h0, h1}, hv1{h2, h3}, lv0{l0, l1}, lv1{l2, l3};
    *(__nv_bfloat162*)(hi + i)     = hv0;
    *(__nv_bfloat162*)(hi + i + 2) = hv1;
    *(__nv_bfloat162*)(lo + i)     = lv0;
    *(__nv_bfloat162*)(lo + i + 2) = lv1;
}

__global__ void cvt_sel_kernel(const float* __restrict__ src, int which,
                               size_t off, int n)
{
    int i = (blockIdx.x * blockDim.x + threadIdx.x) << 2;
    if (i >= n) return;
    __nv_bfloat16 *hi, *lo;
    if (which == 0)      { hi = g_hsH;      lo = g_hsL;      }
    else if (which == 1) { hi = g_WH + off; lo = g_WL + off; }
    else                 { hi = g_WOH;      lo = g_WOL;      }
    cvt4(src, hi, lo, i);
}

__global__ void cvt_ao_kernel()
{
    int i = (blockIdx.x * blockDim.x + threadIdx.x) << 2;
    if (i < S_LEN * QD) cvt4(g_AO, g_AOH, g_AOL, i);
}

// Q/K/V fp32 -> split bf16 (post-RoPE)
__global__ void cvt_qkv_kernel()
{
    int i = (blockIdx.x * blockDim.x + threadIdx.x) << 2;
    const int nq = S_LEN * QD;
    const int nk = S_LEN * KVD;
    if (i < nq)               cvt4(g_Q, g_QH, g_QL, i);
    else if (i < nq + nk)     cvt4(g_K, g_KH, g_KL, i - nq);
    else if (i < nq + 2 * nk) cvt4(g_V, g_VH, g_VL, i - nq - nk);
}

// ---------------------------------------------------------------------------
// RoPE (rotate-half), in place on g_Q and g_K (fp32).
// ---------------------------------------------------------------------------
__global__ void rope_kernel(const float* __restrict__ cosb,
                            const float* __restrict__ sinb)
{
    int idx = blockIdx.x * blockDim.x + threadIdx.x;
    const int qtot = S_LEN * NH * 64;
    const int ktot = S_LEN * NKV * 64;
    if (idx < qtot) {
        int d = idx & 63;
        int h = (idx >> 6) & 31;
        int s = idx >> 11;
        float c  = cosb[s * HD + d];
        float sn = sinb[s * HD + d];
        float* base = g_Q + (size_t)s * QD + h * HD;
        float x1 = base[d], x2 = base[d + 64];
        base[d]      = x1 * c - x2 * sn;
        base[d + 64] = x2 * c + x1 * sn;
    } else if (idx < qtot + ktot) {
        int j = idx - qtot;
        int d = j & 63;
        int h = (j >> 6) & 7;
        int s = j >> 9;
        float c  = cosb[s * HD + d];
        float sn = sinb[s * HD + d];
        float* base = g_K + (size_t)s * KVD + h * HD;
        float x1 = base[d], x2 = base[d + 64];
        base[d]      = x1 * c - x2 * sn;
        base[d + 64] = x2 * c + x1 * sn;
    }
}

// ---------------------------------------------------------------------------
// HMMA causal flash attention (split-bf16, 3-pass for QK and PV).
// 128 threads = 4 warps; BM=64 (16 q-rows/warp), BN=64, HD=128.
// grid = (32 q-tiles reversed, 32 heads). Softmax entirely in registers.
// ---------------------------------------------------------------------------
#define LDF 136
#define FTILE (64*LDF*2)            /* 17408 B */
#define FLASH_SMEM (6*FTILE)        /* 104448 B -> 2 CTAs/SM */

__global__ void __launch_bounds__(128) flash_mma_kernel()
{
    extern __shared__ char fsm[];
    const uint32_t smb = smem_u32(fsm);
    const int tid = threadIdx.x;
    const int w   = tid >> 5;
    const int l   = tid & 31;
    const int qt  = 31 - (int)blockIdx.x;
    const int h   = blockIdx.y;
    const int kvh = h >> 2;

    const uint32_t sQH = smb;
    const uint32_t sQL = smb + FTILE;
    const uint32_t sKH = smb + 2 * FTILE;
    const uint32_t sKL = smb + 3 * FTILE;
    const uint32_t sVH = smb + 4 * FTILE;
    const uint32_t sVL = smb + 5 * FTILE;

    // Load Q tile (64 rows x 128 cols, hi & lo): 1024 16B-chunks each.
    {
        const size_t qbase = (size_t)(qt * 64) * QD + h * HD;
#pragma unroll
        for (int t = 0; t < 8; t++) {
            int idx = tid + t * 128;            // 0..1023
            int row = idx >> 4, c8 = (idx & 15) << 3;
            uint32_t doff = (uint32_t)(row * LDF + c8) * 2;
            cp16(sQH + doff, g_QH + qbase + (size_t)row * QD + c8);
            cp16(sQL + doff, g_QL + qbase + (size_t)row * QD + c8);
        }
        asm volatile("cp.async.commit_group;" ::: "memory");
    }

    float S[8][4];
    float O[16][4] = {};
    float m0 = -1e30f, m1 = -1e30f, lr0 = 0.f, lr1 = 0.f;
    const int row0 = qt * 64 + w * 16 + (l >> 2);   // global q row (and +8)

    for (int jt = 0; jt <= qt; jt++) {
        __syncthreads();                             // prev PV done with V
        {
            const size_t kbase = (size_t)(jt * 64) * KVD + kvh * HD;
#pragma unroll
            for (int t = 0; t < 8; t++) {
                int idx = tid + t * 128;            // 0..1023
                int row = idx >> 4, c8 = (idx & 15) << 3;
                uint32_t doff = (uint32_t)(row * LDF + c8) * 2;
                size_t gs = kbase + (size_t)row * KVD + c8;
                cp16(sKH + doff, g_KH + gs);
                cp16(sKL + doff, g_KL + gs);
                cp16(sVH + doff, g_VH + gs);
                cp16(sVL + doff, g_VL + gs);
            }
            asm volatile("cp.async.commit_group;" ::: "memory");
            asm volatile("cp.async.wait_group 0;" ::: "memory");
        }
        __syncthreads();

        // ---- S = Q K^T (3-pass split) ----
#pragma unroll
        for (int nt = 0; nt < 8; nt++) {
            S[nt][0] = S[nt][1] = S[nt][2] = S[nt][3] = 0.f;
        }
#pragma unroll
        for (int ks = 0; ks < 8; ks++) {
            uint32_t ah[4], al2[4], bh[4][4], bl[4][4];
            uint32_t aoff = (uint32_t)((w * 16 + (l & 15)) * LDF
                                       + ks * 16 + 8 * (l >> 4)) * 2;
            ldsm_x4(ah,  sQH + aoff);
            ldsm_x4(al2, sQL + aoff);
#pragma unroll
            for (int p = 0; p < 4; p++) {
                uint32_t boff = (uint32_t)((p * 16 + 8 * (l >> 4) + (l & 7)) * LDF
                                           + ks * 16 + 8 * ((l >> 3) & 1)) * 2;
                ldsm_x4(bh[p], sKH + boff);
                ldsm_x4(bl[p], sKL + boff);
            }
#pragma unroll
            for (int nt = 0; nt < 8; nt++) {
                const uint32_t* Bh_ = &bh[nt >> 1][(nt & 1) * 2];
                const uint32_t* Bl_ = &bl[nt >> 1][(nt & 1) * 2];
                mma16816(S[nt], ah,  Bh_);
                mma16816(S[nt], ah,  Bl_);
                mma16816(S[nt], al2, Bh_);
            }
        }

        // ---- scale + causal mask ----
        const bool diag = (jt == qt);
#pragma unroll
        for (int nt = 0; nt < 8; nt++)
#pragma unroll
            for (int j = 0; j < 4; j++) {
                float v = S[nt][j] * ATT_SCALE;
                if (diag) {
                    int c = jt * 64 + nt * 8 + 2 * (l & 3) + (j & 1);
                    int r = row0 + (j >> 1) * 8;
                    if (c > r) v = -1e30f;
                }
                S[nt][j] = v;
            }

        // ---- online softmax (registers only) ----
        float mx0 = -1e30f, mx1 = -1e30f;
#pragma unroll
        for (int nt = 0; nt < 8; nt++) {
            mx0 = fmaxf(mx0, fmaxf(S[nt][0], S[nt][1]));
            mx1 = fmaxf(mx1, fmaxf(S[nt][2], S[nt][3]));
        }
        mx0 = fmaxf(mx0, __shfl_xor_sync(0xffffffffu, mx0, 1));
        mx0 = fmaxf(mx0, __shfl_xor_sync(0xffffffffu, mx0, 2));
        mx1 = fmaxf(mx1, __shfl_xor_sync(0xffffffffu, mx1, 1));
        mx1 = fmaxf(mx1, __shfl_xor_sync(0xffffffffu, mx1, 2));
        float mn0 = fmaxf(m0, mx0), mn1 = fmaxf(m1, mx1);
        float a0 = __expf(m0 - mn0), a1 = __expf(m1 - mn1);
        float s0 = 0.f, s1 = 0.f;
#pragma unroll
        for (int nt = 0; nt < 8; nt++) {
            S[nt][0] = __expf(S[nt][0] - mn0);
            S[nt][1] = __expf(S[nt][1] - mn0);
            S[nt][2] = __expf(S[nt][2] - mn1);
            S[nt][3] = __expf(S[nt][3] - mn1);
            s0 += S[nt][0] + S[nt][1];
            s1 += S[nt][2] + S[nt][3];
        }
        s0 += __shfl_xor_sync(0xffffffffu, s0, 1);
        s0 += __shfl_xor_sync(0xffffffffu, s0, 2);
        s1 += __shfl_xor_sync(0xffffffffu, s1, 1);
        s1 += __shfl_xor_sync(0xffffffffu, s1, 2);
        lr0 = lr0 * a0 + s0;
        lr1 = lr1 * a1 + s1;
        m0 = mn0; m1 = mn1;
#pragma unroll
        for (int nt = 0; nt < 16; nt++) {
            O[nt][0] *= a0; O[nt][1] *= a0;
            O[nt][2] *= a1; O[nt][3] *= a1;
        }

        // ---- O += P V (3-pass: PhVh + PhVl + PlVh); V^T via ldmatrix.trans ----
#pragma unroll
        for (int kk = 0; kk < 4; kk++) {
            uint32_t ph[4], pl[4];
            {
                float p00 = S[2 * kk][0],     p01 = S[2 * kk][1];
                float p10 = S[2 * kk][2],     p11 = S[2 * kk][3];
                float p20 = S[2 * kk + 1][0], p21 = S[2 * kk + 1][1];
                float p30 = S[2 * kk + 1][2], p31 = S[2 * kk + 1][3];
                float h00 = __bfloat162float(__float2bfloat16(p00));
                float h01 = __bfloat162float(__float2bfloat16(p01));
                float h10 = __bfloat162float(__float2bfloat16(p10));
                float h11 = __bfloat162float(__float2bfloat16(p11));
                float h20 = __bfloat162float(__float2bfloat16(p20));
                float h21 = __bfloat162float(__float2bfloat16(p21));
                float h30 = __bfloat162float(__float2bfloat16(p30));
                float h31 = __bfloat162float(__float2bfloat16(p31));
                ph[0] = pack_bf(h00, h01); ph[1] = pack_bf(h10, h11);
                ph[2] = pack_bf(h20, h21); ph[3] = pack_bf(h30, h31);
                pl[0] = pack_bf(p00 - h00, p01 - h01);
                pl[1] = pack_bf(p10 - h10, p11 - h11);
                pl[2] = pack_bf(p20 - h20, p21 - h21);
                pl[3] = pack_bf(p30 - h30, p31 - h31);
            }
#pragma unroll
            for (int g = 0; g < 8; g++) {
                uint32_t vh[4], vl[4];
                uint32_t voff = (uint32_t)((kk * 16 + (l & 15)) * LDF
                                           + g * 16 + 8 * (l >> 4)) * 2;
                ldsm_x4_t(vh, sVH + voff);
                ldsm_x4_t(vl, sVL + voff);
                mma16816(O[2 * g],     ph, &vh[0]);
                mma16816(O[2 * g],     ph, &vl[0]);
                mma16816(O[2 * g],     pl, &vh[0]);
                mma16816(O[2 * g + 1], ph, &vh[2]);
                mma16816(O[2 * g + 1], ph, &vl[2]);
                mma16816(O[2 * g + 1], pl, &vh[2]);
            }
        }
    }

    // ---- normalize + write ----
    float inv0 = 1.f / lr0, inv1 = 1.f / lr1;
    const size_t obase = (size_t)row0 * QD + h * HD;
#pragma unroll
    for (int nt = 0; nt < 16; nt++) {
        int col = nt * 8 + 2 * (l & 3);
        float2 v0 = {O[nt][0] * inv0, O[nt][1] * inv0};
        float2 v1 = {O[nt][2] * inv1, O[nt][3] * inv1};
        *(float2*)(g_AO + obase + col)          = v0;
        *(float2*)(g_AO + obase + 8 * QD + col) = v1;
    }
}

// ---------------------------------------------------------------------------
// Launch
// ---------------------------------------------------------------------------
extern "C" void kernel_launch(void* const* d_in, const int* in_sizes, int n_in,
                              void* d_out, int out_size)
{
    const float* hs   = (const float*)d_in[0];
    const float* cosb = (const float*)d_in[1];
    const float* sinb = (const float*)d_in[2];
    const float* wq   = (const float*)d_in[3];
    const float* wk   = (const float*)d_in[4];
    const float* wv   = (const float*)d_in[5];
    const float* wo   = (const float*)d_in[6];
    // d_in[7..9] (k_cache, v_cache, block_ids): scatter/gather is an identity.
    float* out = (float*)d_out;

    cudaFuncSetAttribute(qkv_mma_kernel,
                         cudaFuncAttributeMaxDynamicSharedMemorySize, GEMM_SMEM);
    cudaFuncSetAttribute(o_mma_kernel,
                         cudaFuncAttributeMaxDynamicSharedMemorySize, GEMM_SMEM);
    cudaFuncSetAttribute(flash_mma_kernel,
                         cudaFuncAttributeMaxDynamicSharedMemorySize, FLASH_SMEM);

    // 1) fp32 -> split-bf16 conversions (dst chosen device-side via tag)
    {
        const int nh = S_LEN * HID;
        cvt_sel_kernel<<<nh / 1024, 256>>>(hs, 0, 0, nh);
        const int nq = QD * HID;
        cvt_sel_kernel<<<nq / 1024, 256>>>(wq, 1, 0, nq);
        const int nk = KVD * HID;
        cvt_sel_kernel<<<nk / 1024, 256>>>(wk, 1, (size_t)QD * HID, nk);
        cvt_sel_kernel<<<nk / 1024, 256>>>(wv, 1, (size_t)(QD + KVD) * HID, nk);
        const int no = HID * QD;
        cvt_sel_kernel<<<no / 1024, 256>>>(wo, 2, 0, no);
    }

    // 2) QKV projections on HMMA
    qkv_mma_kernel<<<dim3(48, 16), 256, GEMM_SMEM>>>();

    // 3) RoPE on Q and K (fp32)
    {
        int total = S_LEN * NH * 64 + S_LEN * NKV * 64;
        rope_kernel<<<(total + 255) / 256, 256>>>(cosb, sinb);
    }

    // 4) Q/K/V -> split bf16
    {
        int total = S_LEN * QD + 2 * S_LEN * KVD;
        cvt_qkv_kernel<<<total / 1024, 256>>>();
    }

    // 5) HMMA causal flash attention
    flash_mma_kernel<<<dim3(32, 32), 128, FLASH_SMEM>>>();

    // 6) AO -> split-bf16, then O projection on HMMA
    cvt_ao_kernel<<<(S_LEN * QD) / 1024, 256>>>();
    o_mma_kernel<<<dim3(32, 16), 256, GEMM_SMEM>>>(out);
}